// round 1
// baseline (speedup 1.0000x reference)
#include <cuda_runtime.h>
#include <math.h>

#define Bb 32
#define Nn 2048
#define Mm 512
#define Dd 512

// Scratch (static device globals — allocation-free)
__device__ float g_E[(size_t)Bb * Nn * Mm];   // exp(S)  (128 MB)
__device__ float g_T[(size_t)Bb * Mm * Dd];   // T       (32 MB)
__device__ float g_rowC[Bb * Nn];
__device__ float g_rowQ[Bb * Mm];
__device__ float g_rcpRow[Bb * Nn];
__device__ float g_rcpCol[Bb * Mm];

// ---------------------------------------------------------------------------
// rowC[b,n] = C[b,n,:] . w1     (one warp per row, float4 vectorized)
// ---------------------------------------------------------------------------
__global__ void rowdotC_kernel(const float* __restrict__ C, const float* __restrict__ w)
{
    int warp = (blockIdx.x * blockDim.x + threadIdx.x) >> 5;
    int lane = threadIdx.x & 31;
    if (warp >= Bb * Nn) return;
    const float4* x4 = reinterpret_cast<const float4*>(C + (size_t)warp * Dd);
    const float4* w4 = reinterpret_cast<const float4*>(w);   // w1 = w[0:D]
    float s = 0.f;
#pragma unroll
    for (int j = 0; j < 4; j++) {
        float4 a = x4[lane + j * 32];
        float4 b = w4[lane + j * 32];
        s += a.x * b.x + a.y * b.y + a.z * b.z + a.w * b.w;
    }
#pragma unroll
    for (int o = 16; o; o >>= 1) s += __shfl_xor_sync(~0u, s, o);
    if (lane == 0) g_rowC[warp] = s;
}

__global__ void rowdotQ_kernel(const float* __restrict__ Q, const float* __restrict__ w)
{
    int warp = (blockIdx.x * blockDim.x + threadIdx.x) >> 5;
    int lane = threadIdx.x & 31;
    if (warp >= Bb * Mm) return;
    const float4* x4 = reinterpret_cast<const float4*>(Q + (size_t)warp * Dd);
    const float4* w4 = reinterpret_cast<const float4*>(w + Dd);  // w2 = w[D:2D]
    float s = 0.f;
#pragma unroll
    for (int j = 0; j < 4; j++) {
        float4 a = x4[lane + j * 32];
        float4 b = w4[lane + j * 32];
        s += a.x * b.x + a.y * b.y + a.z * b.z + a.w * b.w;
    }
#pragma unroll
    for (int o = 16; o; o >>= 1) s += __shfl_xor_sync(~0u, s, o);
    if (lane == 0) g_rowQ[warp] = s;
}

// ---------------------------------------------------------------------------
// gemmS: E[b,n,m] = exp( rowC[b,n] + rowQ[b,m] + sum_d (C[b,n,d]*w3[d]) * Q[b,m,d] )
// NT GEMM, 64x64 tile, BK=16, 256 threads, 4x4 per thread.
// ---------------------------------------------------------------------------
__global__ void __launch_bounds__(256) gemmS_kernel(
    const float* __restrict__ C, const float* __restrict__ Q,
    const float* __restrict__ w)
{
    __shared__ float As[16][68];   // [k][n]
    __shared__ float Bs[16][68];   // [k][m]

    const float* w3 = w + 2 * Dd;
    int b  = blockIdx.z;
    int n0 = blockIdx.y * 64;
    int m0 = blockIdx.x * 64;
    int tid = threadIdx.x;
    int tx = tid & 15, ty = tid >> 4;

    const float* Cb = C + (size_t)b * Nn * Dd;
    const float* Qb = Q + (size_t)b * Mm * Dd;

    int lrow = tid >> 2;          // 0..63
    int lk4  = (tid & 3) * 4;     // 0,4,8,12

    float acc[4][4] = {};

    for (int k0 = 0; k0 < Dd; k0 += 16) {
        float4 a  = *reinterpret_cast<const float4*>(Cb + (size_t)(n0 + lrow) * Dd + k0 + lk4);
        float4 wv = *reinterpret_cast<const float4*>(w3 + k0 + lk4);
        a.x *= wv.x; a.y *= wv.y; a.z *= wv.z; a.w *= wv.w;
        float4 bq = *reinterpret_cast<const float4*>(Qb + (size_t)(m0 + lrow) * Dd + k0 + lk4);

        __syncthreads();
        As[lk4 + 0][lrow] = a.x;  As[lk4 + 1][lrow] = a.y;
        As[lk4 + 2][lrow] = a.z;  As[lk4 + 3][lrow] = a.w;
        Bs[lk4 + 0][lrow] = bq.x; Bs[lk4 + 1][lrow] = bq.y;
        Bs[lk4 + 2][lrow] = bq.z; Bs[lk4 + 3][lrow] = bq.w;
        __syncthreads();

#pragma unroll
        for (int k = 0; k < 16; k++) {
            float4 A4 = *reinterpret_cast<const float4*>(&As[k][ty * 4]);
            float4 B4 = *reinterpret_cast<const float4*>(&Bs[k][tx * 4]);
            float av[4] = {A4.x, A4.y, A4.z, A4.w};
            float bv[4] = {B4.x, B4.y, B4.z, B4.w};
#pragma unroll
            for (int i = 0; i < 4; i++)
#pragma unroll
                for (int j = 0; j < 4; j++)
                    acc[i][j] += av[i] * bv[j];
        }
    }

    int n = n0 + ty * 4;
    int m = m0 + tx * 4;
    float rQ0 = g_rowQ[b * Mm + m + 0];
    float rQ1 = g_rowQ[b * Mm + m + 1];
    float rQ2 = g_rowQ[b * Mm + m + 2];
    float rQ3 = g_rowQ[b * Mm + m + 3];
#pragma unroll
    for (int i = 0; i < 4; i++) {
        float rc = g_rowC[b * Nn + n + i];
        float4 o;
        o.x = __expf(acc[i][0] + rc + rQ0);
        o.y = __expf(acc[i][1] + rc + rQ1);
        o.z = __expf(acc[i][2] + rc + rQ2);
        o.w = __expf(acc[i][3] + rc + rQ3);
        *reinterpret_cast<float4*>(&g_E[(size_t)(b * Nn + n + i) * Mm + m]) = o;
    }
}

// ---------------------------------------------------------------------------
// rowsum: rcpRow[b,n] = 1 / sum_m ( Qmask[b,m] ? 0 : E[b,n,m] )
// one warp per row
// ---------------------------------------------------------------------------
__global__ void rowsum_kernel(const int* __restrict__ Qmask)
{
    int warp = (blockIdx.x * blockDim.x + threadIdx.x) >> 5;
    int lane = threadIdx.x & 31;
    if (warp >= Bb * Nn) return;
    int b = warp / Nn;
    const float4* e4 = reinterpret_cast<const float4*>(g_E + (size_t)warp * Mm);
    const int4*   q4 = reinterpret_cast<const int4*>(Qmask + b * Mm);
    float s = 0.f;
#pragma unroll
    for (int j = 0; j < 4; j++) {
        float4 v = e4[lane + j * 32];
        int4   q = q4[lane + j * 32];
        s += (q.x ? 0.f : v.x) + (q.y ? 0.f : v.y) + (q.z ? 0.f : v.z) + (q.w ? 0.f : v.w);
    }
#pragma unroll
    for (int o = 16; o; o >>= 1) s += __shfl_xor_sync(~0u, s, o);
    if (lane == 0) g_rcpRow[warp] = 1.f / s;
}

// ---------------------------------------------------------------------------
// colsum: rcpCol[b,m] = 1 / sum_n ( Cmask[b,n] ? 0 : E[b,n,m] )
// block = 512 threads: 128 columns x 4 n-segments, coalesced over m
// ---------------------------------------------------------------------------
__global__ void __launch_bounds__(512) colsum_kernel(const int* __restrict__ Cmask)
{
    __shared__ float red[512];
    int b   = blockIdx.y;
    int mloc = threadIdx.x & 127;
    int m   = blockIdx.x * 128 + mloc;
    int seg = threadIdx.x >> 7;
    const float* Eb = g_E + (size_t)b * Nn * Mm;
    const int*   cm = Cmask + b * Nn;
    float s = 0.f;
    int nEnd = seg * 512 + 512;
#pragma unroll 4
    for (int n = seg * 512; n < nEnd; n++) {
        float v = Eb[(size_t)n * Mm + m];
        s += cm[n] ? 0.f : v;
    }
    red[threadIdx.x] = s;
    __syncthreads();
    if (threadIdx.x < 128) {
        float t = red[threadIdx.x] + red[threadIdx.x + 128] +
                  red[threadIdx.x + 256] + red[threadIdx.x + 384];
        g_rcpCol[b * Mm + m] = 1.f / t;
    }
}

// ---------------------------------------------------------------------------
// gemmT: T[b,m,d] = rcpCol[b,m] * sum_n ( Cmask[b,n]?0:E[b,n,m] ) * C[b,n,d]
// TN GEMM over K=n (2048). 64x64 tile, BK=16.
// ---------------------------------------------------------------------------
__global__ void __launch_bounds__(256) gemmT_kernel(
    const float* __restrict__ C, const int* __restrict__ Cmask)
{
    __shared__ float As[16][68];   // [k=n][m]
    __shared__ float Bs[16][68];   // [k=n][d]

    int b  = blockIdx.z;
    int m0 = blockIdx.y * 64;
    int d0 = blockIdx.x * 64;
    int tid = threadIdx.x;
    int tx = tid & 15, ty = tid >> 4;

    const float* Eb = g_E + (size_t)b * Nn * Mm;
    const float* Cb = C + (size_t)b * Nn * Dd;
    const int*   cm = Cmask + b * Nn;

    int krow = tid >> 4;          // 0..15 (n within tile)
    int lc4  = (tid & 15) * 4;    // 0..60

    float acc[4][4] = {};

    for (int n0 = 0; n0 < Nn; n0 += 16) {
        int n = n0 + krow;
        float msk = cm[n] ? 0.f : 1.f;
        float4 e = *reinterpret_cast<const float4*>(Eb + (size_t)n * Mm + m0 + lc4);
        float4 c = *reinterpret_cast<const float4*>(Cb + (size_t)n * Dd + d0 + lc4);
        e.x *= msk; e.y *= msk; e.z *= msk; e.w *= msk;

        __syncthreads();
        *reinterpret_cast<float4*>(&As[krow][lc4]) = e;
        *reinterpret_cast<float4*>(&Bs[krow][lc4]) = c;
        __syncthreads();

#pragma unroll
        for (int k = 0; k < 16; k++) {
            float4 A4 = *reinterpret_cast<const float4*>(&As[k][ty * 4]);
            float4 B4 = *reinterpret_cast<const float4*>(&Bs[k][tx * 4]);
            float av[4] = {A4.x, A4.y, A4.z, A4.w};
            float bv[4] = {B4.x, B4.y, B4.z, B4.w};
#pragma unroll
            for (int i = 0; i < 4; i++)
#pragma unroll
                for (int j = 0; j < 4; j++)
                    acc[i][j] += av[i] * bv[j];
        }
    }

    int m = m0 + ty * 4;
    int d = d0 + tx * 4;
#pragma unroll
    for (int i = 0; i < 4; i++) {
        float sc = g_rcpCol[b * Mm + m + i];
        float4 o = {acc[i][0] * sc, acc[i][1] * sc, acc[i][2] * sc, acc[i][3] * sc};
        *reinterpret_cast<float4*>(&g_T[(size_t)(b * Mm + m + i) * Dd + d]) = o;
    }
}

// ---------------------------------------------------------------------------
// gemmAB (fused): for each (b, n-tile, d-tile):
//   A   [b,n,d] = rcpRow[b,n] * sum_m (Qmask?0:E[b,n,m]) * Q[b,m,d]
//   Bout[b,n,d] = rcpRow[b,n] * sum_m (Qmask?0:E[b,n,m]) * T[b,m,d]
// Shares the masked-E tile between both products.
// ---------------------------------------------------------------------------
__global__ void __launch_bounds__(256) gemmAB_kernel(
    const float* __restrict__ Q, const int* __restrict__ Qmask,
    float* __restrict__ outA, float* __restrict__ outB)
{
    __shared__ float Es[16][68];   // [k=m][n]
    __shared__ float Qs[16][68];   // [k=m][d]
    __shared__ float Ts[16][68];   // [k=m][d]

    int b  = blockIdx.z;
    int n0 = blockIdx.y * 64;
    int d0 = blockIdx.x * 64;
    int tid = threadIdx.x;
    int tx = tid & 15, ty = tid >> 4;

    const float* Eb = g_E + (size_t)b * Nn * Mm;
    const float* Qb = Q + (size_t)b * Mm * Dd;
    const float* Tb = g_T + (size_t)b * Mm * Dd;
    const int*   qm = Qmask + b * Mm;

    int lrow = tid >> 2;          // 0..63 (n)
    int lk4  = (tid & 3) * 4;     // m-sub 0,4,8,12
    int krow = tid >> 4;          // 0..15 (m)
    int lc4  = (tid & 15) * 4;    // d-sub

    float accA[4][4] = {};
    float accB[4][4] = {};

    for (int m0 = 0; m0 < Mm; m0 += 16) {
        float4 e = *reinterpret_cast<const float4*>(Eb + (size_t)(n0 + lrow) * Mm + m0 + lk4);
        int4 mq = *reinterpret_cast<const int4*>(qm + m0 + lk4);
        e.x = mq.x ? 0.f : e.x;
        e.y = mq.y ? 0.f : e.y;
        e.z = mq.z ? 0.f : e.z;
        e.w = mq.w ? 0.f : e.w;
        float4 q = *reinterpret_cast<const float4*>(Qb + (size_t)(m0 + krow) * Dd + d0 + lc4);
        float4 t = *reinterpret_cast<const float4*>(Tb + (size_t)(m0 + krow) * Dd + d0 + lc4);

        __syncthreads();
        Es[lk4 + 0][lrow] = e.x; Es[lk4 + 1][lrow] = e.y;
        Es[lk4 + 2][lrow] = e.z; Es[lk4 + 3][lrow] = e.w;
        *reinterpret_cast<float4*>(&Qs[krow][lc4]) = q;
        *reinterpret_cast<float4*>(&Ts[krow][lc4]) = t;
        __syncthreads();

#pragma unroll
        for (int k = 0; k < 16; k++) {
            float4 E4 = *reinterpret_cast<const float4*>(&Es[k][ty * 4]);
            float4 Q4 = *reinterpret_cast<const float4*>(&Qs[k][tx * 4]);
            float4 T4 = *reinterpret_cast<const float4*>(&Ts[k][tx * 4]);
            float ev[4] = {E4.x, E4.y, E4.z, E4.w};
            float qv[4] = {Q4.x, Q4.y, Q4.z, Q4.w};
            float tv[4] = {T4.x, T4.y, T4.z, T4.w};
#pragma unroll
            for (int i = 0; i < 4; i++)
#pragma unroll
                for (int j = 0; j < 4; j++) {
                    accA[i][j] += ev[i] * qv[j];
                    accB[i][j] += ev[i] * tv[j];
                }
        }
    }

    int n = n0 + ty * 4;
    int d = d0 + tx * 4;
#pragma unroll
    for (int i = 0; i < 4; i++) {
        float sc = g_rcpRow[b * Nn + n + i];
        size_t idx = (size_t)(b * Nn + n + i) * Dd + d;
        float4 oa = {accA[i][0] * sc, accA[i][1] * sc, accA[i][2] * sc, accA[i][3] * sc};
        float4 ob = {accB[i][0] * sc, accB[i][1] * sc, accB[i][2] * sc, accB[i][3] * sc};
        *reinterpret_cast<float4*>(&outA[idx]) = oa;
        *reinterpret_cast<float4*>(&outB[idx]) = ob;
    }
}

// ---------------------------------------------------------------------------
extern "C" void kernel_launch(void* const* d_in, const int* in_sizes, int n_in,
                              void* d_out, int out_size)
{
    const float* C     = (const float*)d_in[0];
    const float* Q     = (const float*)d_in[1];
    const int*   Cmask = (const int*)d_in[2];
    const int*   Qmask = (const int*)d_in[3];
    const float* w     = (const float*)d_in[4];

    float* outA = (float*)d_out;
    float* outB = outA + (size_t)Bb * Nn * Dd;

    // 1. row dots
    rowdotC_kernel<<<(Bb * Nn) / 8, 256>>>(C, w);
    rowdotQ_kernel<<<(Bb * Mm) / 8, 256>>>(Q, w);

    // 2. E = exp(S)
    dim3 gS(Mm / 64, Nn / 64, Bb);
    gemmS_kernel<<<gS, 256>>>(C, Q, w);

    // 3. masked row/col sums -> reciprocals
    rowsum_kernel<<<(Bb * Nn) / 8, 256>>>(Qmask);
    dim3 gCS(Mm / 128, Bb);
    colsum_kernel<<<gCS, 512>>>(Cmask);

    // 4. T
    dim3 gT(Dd / 64, Mm / 64, Bb);
    gemmT_kernel<<<gT, 256>>>(C, Cmask);

    // 5. A and Bout (fused)
    dim3 gAB(Dd / 64, Nn / 64, Bb);
    gemmAB_kernel<<<gAB, 256>>>(Q, Qmask, outA, outB);
}

// round 3
// speedup vs baseline: 1.4551x; 1.4551x over previous
#include <cuda_runtime.h>
#include <cuda_bf16.h>
#include <cstdint>
#include <math.h>

#define Bb 32
#define Nn 2048
#define Mm 512
#define Dd 512

#define BM 128
#define BN 64
#define BK 32
#define PK 40   // smem pitch in bf16 elements (conflict-free for ldmatrix)

// ---------------------------------------------------------------------------
// Scratch (static device globals — allocation-free)
// ---------------------------------------------------------------------------
__device__ float g_E [(size_t)Bb*Nn*Mm];   // exp(S)   [b][n][m]
__device__ float g_Et[(size_t)Bb*Nn*Mm];   // E^T      [b][m][n]
__device__ float g_Ct[(size_t)Bb*Nn*Dd];   // C^T      [b][d][n]
__device__ float g_Qt[(size_t)Bb*Mm*Dd];   // Q^T      [b][d][m]
__device__ float g_Tt[(size_t)Bb*Mm*Dd];   // T^T      [b][d][m]
__device__ float g_rowC[Bb*Nn];
__device__ float g_rowQ[Bb*Mm];
__device__ float g_rcpRow[Bb*Nn];
__device__ float g_rcpCol[Bb*Mm];

// ---------------------------------------------------------------------------
// MMA helpers (baseline PTX — no 'a' features)
// ---------------------------------------------------------------------------
__device__ __forceinline__ uint32_t smem_u32(const void* p){
    uint32_t a;
    asm("{ .reg .u64 t; cvta.to.shared.u64 t, %1; cvt.u32.u64 %0, t; }"
        : "=r"(a) : "l"(p));
    return a;
}

__device__ __forceinline__ void ldm_x4(uint32_t* r, const uint16_t* p){
    uint32_t a = smem_u32(p);
    asm volatile("ldmatrix.sync.aligned.m8n8.x4.shared.b16 {%0,%1,%2,%3}, [%4];"
        : "=r"(r[0]), "=r"(r[1]), "=r"(r[2]), "=r"(r[3]) : "r"(a));
}

__device__ __forceinline__ void mma_bf16(float* c, const uint32_t* a,
                                         uint32_t b0, uint32_t b1){
    asm volatile("mma.sync.aligned.m16n8k16.row.col.f32.bf16.bf16.f32 "
        "{%0,%1,%2,%3}, {%4,%5,%6,%7}, {%8,%9}, {%0,%1,%2,%3};"
        : "+f"(c[0]), "+f"(c[1]), "+f"(c[2]), "+f"(c[3])
        : "r"(a[0]), "r"(a[1]), "r"(a[2]), "r"(a[3]), "r"(b0), "r"(b1));
}

// ---------------------------------------------------------------------------
// Tile staging: fp32 [row][k] K-major -> bf16 hi/lo smem tiles (pitch PK).
// Optional per-k weight (w3) and per-k int mask (zero where mask != 0).
// ---------------------------------------------------------------------------
template<int ROWS>
__device__ __forceinline__ void stage(
    const float* __restrict__ src, int pitch, int r0, int k0,
    uint16_t* __restrict__ hi, uint16_t* __restrict__ lo,
    const float* __restrict__ wvec, const int* __restrict__ kmask, int tid)
{
    int rr = tid >> 3;            // 0..31
    int c4 = (tid & 7) * 4;       // 0,4,...,28
    float4 wv = make_float4(1.f, 1.f, 1.f, 1.f);
    if (wvec) wv = *reinterpret_cast<const float4*>(wvec + k0 + c4);
    int4 mk = make_int4(0, 0, 0, 0);
    if (kmask) mk = *reinterpret_cast<const int4*>(kmask + k0 + c4);
#pragma unroll
    for (int it = 0; it < ROWS/32; it++){
        int r = rr + it*32;
        float4 v = *reinterpret_cast<const float4*>(src + (size_t)(r0 + r)*pitch + k0 + c4);
        v.x *= wv.x; v.y *= wv.y; v.z *= wv.z; v.w *= wv.w;
        if (kmask){
            v.x = mk.x ? 0.f : v.x;  v.y = mk.y ? 0.f : v.y;
            v.z = mk.z ? 0.f : v.z;  v.w = mk.w ? 0.f : v.w;
        }
        __nv_bfloat16 hx = __float2bfloat16_rn(v.x);
        __nv_bfloat16 hy = __float2bfloat16_rn(v.y);
        __nv_bfloat16 hz = __float2bfloat16_rn(v.z);
        __nv_bfloat16 hw = __float2bfloat16_rn(v.w);
        __nv_bfloat16 lx = __float2bfloat16_rn(v.x - __bfloat162float(hx));
        __nv_bfloat16 ly = __float2bfloat16_rn(v.y - __bfloat162float(hy));
        __nv_bfloat16 lz = __float2bfloat16_rn(v.z - __bfloat162float(hz));
        __nv_bfloat16 lw = __float2bfloat16_rn(v.w - __bfloat162float(hw));
        uint32_t off = r*PK + c4;
        *reinterpret_cast<__nv_bfloat162*>(hi + off)     = __halves2bfloat162(hx, hy);
        *reinterpret_cast<__nv_bfloat162*>(hi + off + 2) = __halves2bfloat162(hz, hw);
        *reinterpret_cast<__nv_bfloat162*>(lo + off)     = __halves2bfloat162(lx, ly);
        *reinterpret_cast<__nv_bfloat162*>(lo + off + 2) = __halves2bfloat162(lz, lw);
    }
}

// ---------------------------------------------------------------------------
// Warp mainloop body: accumulate one staged BK=32 chunk into acc[2][4][4]
// (warp tile 32x32), bf16x3: hi*hi + hi*lo + lo*hi.
// ---------------------------------------------------------------------------
__device__ __forceinline__ void warp_mma_tile(
    float acc[2][4][4],
    const uint16_t* __restrict__ Ahi, const uint16_t* __restrict__ Alo,
    const uint16_t* __restrict__ Bhi, const uint16_t* __restrict__ Blo,
    int wm, int wn, int lane)
{
    int rsel = lane & 15;
    int ksel = (lane >> 4) * 8;
#pragma unroll
    for (int ks = 0; ks < 2; ks++){
        uint32_t ah[2][4], al[2][4];
#pragma unroll
        for (int mt = 0; mt < 2; mt++){
            ldm_x4(ah[mt], Ahi + (wm*32 + mt*16 + rsel)*PK + ks*16 + ksel);
            ldm_x4(al[mt], Alo + (wm*32 + mt*16 + rsel)*PK + ks*16 + ksel);
        }
        uint32_t bh[2][4], bl[2][4];
#pragma unroll
        for (int g = 0; g < 2; g++){
            ldm_x4(bh[g], Bhi + (wn*32 + g*16 + rsel)*PK + ks*16 + ksel);
            ldm_x4(bl[g], Blo + (wn*32 + g*16 + rsel)*PK + ks*16 + ksel);
        }
#pragma unroll
        for (int mt = 0; mt < 2; mt++)
#pragma unroll
        for (int nt = 0; nt < 4; nt++){
            uint32_t b0h = bh[nt>>1][nt & 1], b1h = bh[nt>>1][(nt & 1) + 2];
            uint32_t b0l = bl[nt>>1][nt & 1], b1l = bl[nt>>1][(nt & 1) + 2];
            mma_bf16(acc[mt][nt], ah[mt], b0h, b1h);
            mma_bf16(acc[mt][nt], ah[mt], b0l, b1l);
            mma_bf16(acc[mt][nt], al[mt], b0h, b1h);
        }
    }
}

// ---------------------------------------------------------------------------
// gemmS: E[b,n,m] = exp( rowC[n] + rowQ[m] + sum_d (C*w3)[n,d]*Q[m,d] )
// ---------------------------------------------------------------------------
__global__ void __launch_bounds__(256) gemmS_mma(
    const float* __restrict__ C, const float* __restrict__ Q,
    const float* __restrict__ w)
{
    __shared__ uint16_t Ah[BM*PK], Al[BM*PK], Bh[BN*PK], Bl[BN*PK];
    int tid = threadIdx.x, lane = tid & 31, wid = tid >> 5;
    int wm = wid >> 1, wn = wid & 1;
    int b = blockIdx.z, n0 = blockIdx.y*BM, m0 = blockIdx.x*BN;
    const float* Cb = C + (size_t)b*Nn*Dd;
    const float* Qb = Q + (size_t)b*Mm*Dd;
    const float* w3 = w + 2*Dd;

    float acc[2][4][4] = {};
    for (int k0 = 0; k0 < Dd; k0 += BK){
        __syncthreads();
        stage<BM>(Cb, Dd, n0, k0, Ah, Al, w3, nullptr, tid);
        stage<BN>(Qb, Dd, m0, k0, Bh, Bl, nullptr, nullptr, tid);
        __syncthreads();
        warp_mma_tile(acc, Ah, Al, Bh, Bl, wm, wn, lane);
    }

    int rg = lane >> 2, cg = (lane & 3)*2;
#pragma unroll
    for (int mt = 0; mt < 2; mt++)
#pragma unroll
    for (int nt = 0; nt < 4; nt++)
#pragma unroll
    for (int h = 0; h < 2; h++){
        int n = n0 + wm*32 + mt*16 + rg + h*8;
        int m = m0 + wn*32 + nt*8 + cg;
        float rc = g_rowC[b*Nn + n];
        float2 o;
        o.x = __expf(acc[mt][nt][h*2+0] + rc + g_rowQ[b*Mm + m + 0]);
        o.y = __expf(acc[mt][nt][h*2+1] + rc + g_rowQ[b*Mm + m + 1]);
        *reinterpret_cast<float2*>(&g_E[(size_t)(b*Nn + n)*Mm + m]) = o;
    }
}

// ---------------------------------------------------------------------------
// gemmT: Tt[b,d,m] = rcpCol[m] * sum_n Ct[d,n] * (Cmask[n]? 0 : Et[m,n])
// ---------------------------------------------------------------------------
__global__ void __launch_bounds__(256) gemmT_mma(const int* __restrict__ Cmask)
{
    __shared__ uint16_t Ah[BM*PK], Al[BM*PK], Bh[BN*PK], Bl[BN*PK];
    int tid = threadIdx.x, lane = tid & 31, wid = tid >> 5;
    int wm = wid >> 1, wn = wid & 1;
    int b = blockIdx.z, d0 = blockIdx.y*BM, m0 = blockIdx.x*BN;
    const float* Ab = g_Ct + (size_t)b*Dd*Nn;   // [d][n]
    const float* Bp = g_Et + (size_t)b*Mm*Nn;   // [m][n]
    const int*   cm = Cmask + b*Nn;

    float acc[2][4][4] = {};
    for (int k0 = 0; k0 < Nn; k0 += BK){
        __syncthreads();
        stage<BM>(Ab, Nn, d0, k0, Ah, Al, nullptr, nullptr, tid);
        stage<BN>(Bp, Nn, m0, k0, Bh, Bl, nullptr, cm, tid);
        __syncthreads();
        warp_mma_tile(acc, Ah, Al, Bh, Bl, wm, wn, lane);
    }

    int rg = lane >> 2, cg = (lane & 3)*2;
#pragma unroll
    for (int mt = 0; mt < 2; mt++)
#pragma unroll
    for (int nt = 0; nt < 4; nt++)
#pragma unroll
    for (int h = 0; h < 2; h++){
        int d = d0 + wm*32 + mt*16 + rg + h*8;
        int m = m0 + wn*32 + nt*8 + cg;
        float2 o;
        o.x = acc[mt][nt][h*2+0] * g_rcpCol[b*Mm + m + 0];
        o.y = acc[mt][nt][h*2+1] * g_rcpCol[b*Mm + m + 1];
        *reinterpret_cast<float2*>(&g_Tt[((size_t)b*Dd + d)*Mm + m]) = o;
    }
}

// ---------------------------------------------------------------------------
// gemmAB: A   [b,n,d] = rcpRow[n] * sum_m E[n,m] * (Qmask[m]? 0 : Qt[d,m])
//         Bout[b,n,d] = rcpRow[n] * sum_m E[n,m] * (Qmask[m]? 0 : Tt[d,m])
// ---------------------------------------------------------------------------
__global__ void __launch_bounds__(256) gemmAB_mma(
    const int* __restrict__ Qmask, float* __restrict__ outA,
    float* __restrict__ outB)
{
    __shared__ uint16_t Ah[BM*PK], Al[BM*PK];
    __shared__ uint16_t B1h[BN*PK], B1l[BN*PK], B2h[BN*PK], B2l[BN*PK];
    int tid = threadIdx.x, lane = tid & 31, wid = tid >> 5;
    int wm = wid >> 1, wn = wid & 1;
    int b = blockIdx.z, n0 = blockIdx.y*BM, d0 = blockIdx.x*BN;
    const float* Eb  = g_E  + (size_t)b*Nn*Mm;   // [n][m]
    const float* Qtb = g_Qt + (size_t)b*Dd*Mm;   // [d][m]
    const float* Ttb = g_Tt + (size_t)b*Dd*Mm;   // [d][m]
    const int*   qm  = Qmask + b*Mm;

    float accA[2][4][4] = {};
    float accB[2][4][4] = {};
    for (int k0 = 0; k0 < Mm; k0 += BK){
        __syncthreads();
        stage<BM>(Eb,  Mm, n0, k0, Ah,  Al,  nullptr, nullptr, tid);
        stage<BN>(Qtb, Mm, d0, k0, B1h, B1l, nullptr, qm, tid);
        stage<BN>(Ttb, Mm, d0, k0, B2h, B2l, nullptr, qm, tid);
        __syncthreads();
        warp_mma_tile(accA, Ah, Al, B1h, B1l, wm, wn, lane);
        warp_mma_tile(accB, Ah, Al, B2h, B2l, wm, wn, lane);
    }

    int rg = lane >> 2, cg = (lane & 3)*2;
#pragma unroll
    for (int mt = 0; mt < 2; mt++)
#pragma unroll
    for (int nt = 0; nt < 4; nt++)
#pragma unroll
    for (int h = 0; h < 2; h++){
        int n = n0 + wm*32 + mt*16 + rg + h*8;
        int d = d0 + wn*32 + nt*8 + cg;
        float rr = g_rcpRow[b*Nn + n];
        size_t idx = (size_t)(b*Nn + n)*Dd + d;
        float2 oa = { accA[mt][nt][h*2+0]*rr, accA[mt][nt][h*2+1]*rr };
        float2 ob = { accB[mt][nt][h*2+0]*rr, accB[mt][nt][h*2+1]*rr };
        *reinterpret_cast<float2*>(&outA[idx]) = oa;
        *reinterpret_cast<float2*>(&outB[idx]) = ob;
    }
}

// ---------------------------------------------------------------------------
// Row-dot kernels
// ---------------------------------------------------------------------------
__global__ void rowdotC_kernel(const float* __restrict__ C, const float* __restrict__ w)
{
    int warp = (blockIdx.x * blockDim.x + threadIdx.x) >> 5;
    int lane = threadIdx.x & 31;
    if (warp >= Bb * Nn) return;
    const float4* x4 = reinterpret_cast<const float4*>(C + (size_t)warp * Dd);
    const float4* w4 = reinterpret_cast<const float4*>(w);
    float s = 0.f;
#pragma unroll
    for (int j = 0; j < 4; j++){
        float4 a = x4[lane + j*32]; float4 b = w4[lane + j*32];
        s += a.x*b.x + a.y*b.y + a.z*b.z + a.w*b.w;
    }
#pragma unroll
    for (int o = 16; o; o >>= 1) s += __shfl_xor_sync(~0u, s, o);
    if (lane == 0) g_rowC[warp] = s;
}

__global__ void rowdotQ_kernel(const float* __restrict__ Q, const float* __restrict__ w)
{
    int warp = (blockIdx.x * blockDim.x + threadIdx.x) >> 5;
    int lane = threadIdx.x & 31;
    if (warp >= Bb * Mm) return;
    const float4* x4 = reinterpret_cast<const float4*>(Q + (size_t)warp * Dd);
    const float4* w4 = reinterpret_cast<const float4*>(w + Dd);
    float s = 0.f;
#pragma unroll
    for (int j = 0; j < 4; j++){
        float4 a = x4[lane + j*32]; float4 b = w4[lane + j*32];
        s += a.x*b.x + a.y*b.y + a.z*b.z + a.w*b.w;
    }
#pragma unroll
    for (int o = 16; o; o >>= 1) s += __shfl_xor_sync(~0u, s, o);
    if (lane == 0) g_rowQ[warp] = s;
}

// ---------------------------------------------------------------------------
// Transpose kernels (32x32 tiles)
// ---------------------------------------------------------------------------
__device__ __forceinline__ void transpose_body(
    const float* __restrict__ src, float* __restrict__ dst, int rows, int cols)
{
    __shared__ float t[32][33];
    int b = blockIdx.z;
    const float* s = src + (size_t)b*rows*cols;
    float* d = dst + (size_t)b*rows*cols;
    int c0 = blockIdx.x*32, r0 = blockIdx.y*32;
    int tx = threadIdx.x & 31, ty = threadIdx.x >> 5;
#pragma unroll
    for (int j = 0; j < 4; j++)
        t[ty + 8*j][tx] = s[(size_t)(r0 + ty + 8*j)*cols + c0 + tx];
    __syncthreads();
#pragma unroll
    for (int j = 0; j < 4; j++)
        d[(size_t)(c0 + ty + 8*j)*rows + r0 + tx] = t[tx][ty + 8*j];
}
__global__ void __launch_bounds__(256) transposeC_kernel(const float* __restrict__ C)
{ transpose_body(C, g_Ct, Nn, Dd); }
__global__ void __launch_bounds__(256) transposeQ_kernel(const float* __restrict__ Q)
{ transpose_body(Q, g_Qt, Mm, Dd); }
__global__ void __launch_bounds__(256) transposeE_kernel()
{ transpose_body(g_E, g_Et, Nn, Mm); }

// ---------------------------------------------------------------------------
// Masked reductions -> reciprocals
// ---------------------------------------------------------------------------
__global__ void rowsum_kernel(const int* __restrict__ Qmask)
{
    int warp = (blockIdx.x * blockDim.x + threadIdx.x) >> 5;
    int lane = threadIdx.x & 31;
    if (warp >= Bb * Nn) return;
    int b = warp / Nn;
    const float4* e4 = reinterpret_cast<const float4*>(g_E + (size_t)warp * Mm);
    const int4*   q4 = reinterpret_cast<const int4*>(Qmask + b * Mm);
    float s = 0.f;
#pragma unroll
    for (int j = 0; j < 4; j++){
        float4 v = e4[lane + j*32];
        int4   q = q4[lane + j*32];
        s += (q.x ? 0.f : v.x) + (q.y ? 0.f : v.y) + (q.z ? 0.f : v.z) + (q.w ? 0.f : v.w);
    }
#pragma unroll
    for (int o = 16; o; o >>= 1) s += __shfl_xor_sync(~0u, s, o);
    if (lane == 0) g_rcpRow[warp] = 1.f / s;
}

__global__ void colsumT_kernel(const int* __restrict__ Cmask)
{
    int warp = (blockIdx.x * blockDim.x + threadIdx.x) >> 5;
    int lane = threadIdx.x & 31;
    if (warp >= Bb * Mm) return;
    int b = warp / Mm;
    const float4* e4 = reinterpret_cast<const float4*>(g_Et + (size_t)warp * Nn);
    const int4*   c4 = reinterpret_cast<const int4*>(Cmask + b * Nn);
    float s = 0.f;
#pragma unroll
    for (int j = 0; j < 16; j++){
        float4 v = e4[lane + j*32];
        int4   c = c4[lane + j*32];
        s += (c.x ? 0.f : v.x) + (c.y ? 0.f : v.y) + (c.z ? 0.f : v.z) + (c.w ? 0.f : v.w);
    }
#pragma unroll
    for (int o = 16; o; o >>= 1) s += __shfl_xor_sync(~0u, s, o);
    if (lane == 0) g_rcpCol[warp] = 1.f / s;
}

// ---------------------------------------------------------------------------
extern "C" void kernel_launch(void* const* d_in, const int* in_sizes, int n_in,
                              void* d_out, int out_size)
{
    const float* C     = (const float*)d_in[0];
    const float* Q     = (const float*)d_in[1];
    const int*   Cmask = (const int*)d_in[2];
    const int*   Qmask = (const int*)d_in[3];
    const float* w     = (const float*)d_in[4];

    float* outA = (float*)d_out;
    float* outB = outA + (size_t)Bb * Nn * Dd;

    // 1. row dots + input transposes
    rowdotC_kernel<<<(Bb*Nn)/8, 256>>>(C, w);
    rowdotQ_kernel<<<(Bb*Mm)/8, 256>>>(Q, w);
    transposeC_kernel<<<dim3(Dd/32, Nn/32, Bb), 256>>>(C);
    transposeQ_kernel<<<dim3(Dd/32, Mm/32, Bb), 256>>>(Q);

    // 2. E = exp(S)   (tensor core, bf16x3)
    gemmS_mma<<<dim3(Mm/BN, Nn/BM, Bb), 256>>>(C, Q, w);

    // 3. E^T + masked reductions
    transposeE_kernel<<<dim3(Mm/32, Nn/32, Bb), 256>>>();
    rowsum_kernel<<<(Bb*Nn)/8, 256>>>(Qmask);
    colsumT_kernel<<<(Bb*Mm)/8, 256>>>(Cmask);

    // 4. T^T (tensor core)
    gemmT_mma<<<dim3(Mm/BN, Dd/BM, Bb), 256>>>(Cmask);

    // 5. A and Bout (tensor core, fused)
    gemmAB_mma<<<dim3(Dd/BN, Nn/BM, Bb), 256>>>(Qmask, outA, outB);
}

// round 5
// speedup vs baseline: 2.0261x; 1.3924x over previous
#include <cuda_runtime.h>
#include <cuda_bf16.h>
#include <cstdint>
#include <math.h>

#define Bb 32
#define Nn 2048
#define Mm 512
#define Dd 512

#define BM 128
#define BN 64
#define BK 32
#define PK 40   // smem pitch in bf16 elements (conflict-free for ldmatrix)

// ---------------------------------------------------------------------------
// Scratch (static device globals — allocation-free)
// ---------------------------------------------------------------------------
__device__ float g_E [(size_t)Bb*Nn*Mm];   // exp(S)   [b][n][m]
__device__ float g_Et[(size_t)Bb*Nn*Mm];   // E^T      [b][m][n]
__device__ float g_Ct[(size_t)Bb*Nn*Dd];   // C^T      [b][d][n]
__device__ float g_Qt[(size_t)Bb*Mm*Dd];   // Q^T      [b][d][m]
__device__ float g_Tt[(size_t)Bb*Mm*Dd];   // T^T      [b][d][m]
__device__ float g_rowC[Bb*Nn];
__device__ float g_rowQ[Bb*Mm];
__device__ float g_rcpRow[Bb*Nn];
__device__ float g_rcpCol[Bb*Mm];

// ---------------------------------------------------------------------------
// MMA helpers (baseline PTX — no 'a' features)
// ---------------------------------------------------------------------------
__device__ __forceinline__ uint32_t smem_u32(const void* p){
    uint32_t a;
    asm("{ .reg .u64 t; cvta.to.shared.u64 t, %1; cvt.u32.u64 %0, t; }"
        : "=r"(a) : "l"(p));
    return a;
}

__device__ __forceinline__ void ldm_x4(uint32_t* r, const uint16_t* p){
    uint32_t a = smem_u32(p);
    asm volatile("ldmatrix.sync.aligned.m8n8.x4.shared.b16 {%0,%1,%2,%3}, [%4];"
        : "=r"(r[0]), "=r"(r[1]), "=r"(r[2]), "=r"(r[3]) : "r"(a));
}

__device__ __forceinline__ void mma_bf16(float* c, const uint32_t* a,
                                         uint32_t b0, uint32_t b1){
    asm volatile("mma.sync.aligned.m16n8k16.row.col.f32.bf16.bf16.f32 "
        "{%0,%1,%2,%3}, {%4,%5,%6,%7}, {%8,%9}, {%0,%1,%2,%3};"
        : "+f"(c[0]), "+f"(c[1]), "+f"(c[2]), "+f"(c[3])
        : "r"(a[0]), "r"(a[1]), "r"(a[2]), "r"(a[3]), "r"(b0), "r"(b1));
}

// ---------------------------------------------------------------------------
// Register fragments for double-buffered global loads
// ---------------------------------------------------------------------------
template<int ROWS>
struct TileFrag { float4 v[ROWS/32]; };

template<int ROWS>
__device__ __forceinline__ void frag_load(TileFrag<ROWS>& f,
    const float* __restrict__ src, int pitch, int r0, int k0, int tid)
{
    int rr = tid >> 3;            // 0..31
    int c4 = (tid & 7) * 4;       // 0,4,...,28
#pragma unroll
    for (int it = 0; it < ROWS/32; it++)
        f.v[it] = *reinterpret_cast<const float4*>(
            src + (size_t)(r0 + rr + it*32)*pitch + k0 + c4);
}

// Convert staged fragment -> bf16 hi/lo smem tiles (pitch PK).
// Optional per-k weight (w3) and per-k int mask (zero where mask != 0).
template<int ROWS>
__device__ __forceinline__ void frag_stage(const TileFrag<ROWS>& f,
    uint16_t* __restrict__ hi, uint16_t* __restrict__ lo,
    const float* __restrict__ wvec, const int* __restrict__ kmask,
    int k0, int tid)
{
    int rr = tid >> 3;
    int c4 = (tid & 7) * 4;
    float4 wv = make_float4(1.f, 1.f, 1.f, 1.f);
    if (wvec) wv = *reinterpret_cast<const float4*>(wvec + k0 + c4);
    int4 mk = make_int4(0, 0, 0, 0);
    if (kmask) mk = *reinterpret_cast<const int4*>(kmask + k0 + c4);
#pragma unroll
    for (int it = 0; it < ROWS/32; it++){
        int r = rr + it*32;
        float4 v = f.v[it];
        v.x *= wv.x; v.y *= wv.y; v.z *= wv.z; v.w *= wv.w;
        if (kmask){
            v.x = mk.x ? 0.f : v.x;  v.y = mk.y ? 0.f : v.y;
            v.z = mk.z ? 0.f : v.z;  v.w = mk.w ? 0.f : v.w;
        }
        __nv_bfloat16 hx = __float2bfloat16_rn(v.x);
        __nv_bfloat16 hy = __float2bfloat16_rn(v.y);
        __nv_bfloat16 hz = __float2bfloat16_rn(v.z);
        __nv_bfloat16 hw = __float2bfloat16_rn(v.w);
        __nv_bfloat16 lx = __float2bfloat16_rn(v.x - __bfloat162float(hx));
        __nv_bfloat16 ly = __float2bfloat16_rn(v.y - __bfloat162float(hy));
        __nv_bfloat16 lz = __float2bfloat16_rn(v.z - __bfloat162float(hz));
        __nv_bfloat16 lw = __float2bfloat16_rn(v.w - __bfloat162float(hw));
        uint32_t off = r*PK + c4;
        *reinterpret_cast<__nv_bfloat162*>(hi + off)     = __halves2bfloat162(hx, hy);
        *reinterpret_cast<__nv_bfloat162*>(hi + off + 2) = __halves2bfloat162(hz, hw);
        *reinterpret_cast<__nv_bfloat162*>(lo + off)     = __halves2bfloat162(lx, ly);
        *reinterpret_cast<__nv_bfloat162*>(lo + off + 2) = __halves2bfloat162(lz, lw);
    }
}

// ---------------------------------------------------------------------------
// Warp mainloop body: accumulate one staged BK=32 chunk into acc[2][4][4]
// (warp tile 32x32), bf16x3: hi*hi + hi*lo + lo*hi.
// ---------------------------------------------------------------------------
__device__ __forceinline__ void warp_mma_tile(
    float acc[2][4][4],
    const uint16_t* __restrict__ Ahi, const uint16_t* __restrict__ Alo,
    const uint16_t* __restrict__ Bhi, const uint16_t* __restrict__ Blo,
    int wm, int wn, int lane)
{
    int rsel = lane & 15;
    int ksel = (lane >> 4) * 8;
#pragma unroll
    for (int ks = 0; ks < 2; ks++){
        uint32_t ah[2][4], al[2][4];
#pragma unroll
        for (int mt = 0; mt < 2; mt++){
            ldm_x4(ah[mt], Ahi + (wm*32 + mt*16 + rsel)*PK + ks*16 + ksel);
            ldm_x4(al[mt], Alo + (wm*32 + mt*16 + rsel)*PK + ks*16 + ksel);
        }
        uint32_t bh[2][4], bl[2][4];
#pragma unroll
        for (int g = 0; g < 2; g++){
            ldm_x4(bh[g], Bhi + (wn*32 + g*16 + rsel)*PK + ks*16 + ksel);
            ldm_x4(bl[g], Blo + (wn*32 + g*16 + rsel)*PK + ks*16 + ksel);
        }
#pragma unroll
        for (int mt = 0; mt < 2; mt++)
#pragma unroll
        for (int nt = 0; nt < 4; nt++){
            uint32_t b0h = bh[nt>>1][nt & 1], b1h = bh[nt>>1][(nt & 1) + 2];
            uint32_t b0l = bl[nt>>1][nt & 1], b1l = bl[nt>>1][(nt & 1) + 2];
            mma_bf16(acc[mt][nt], ah[mt], b0h, b1h);
            mma_bf16(acc[mt][nt], ah[mt], b0l, b1l);
            mma_bf16(acc[mt][nt], al[mt], b0h, b1h);
        }
    }
}

// ---------------------------------------------------------------------------
// gemmS: E[b,n,m] = exp( rowC[n] + rowQ[m] + sum_d (C*w3)[n,d]*Q[m,d] )
// ---------------------------------------------------------------------------
__global__ void __launch_bounds__(256) gemmS_mma(
    const float* __restrict__ C, const float* __restrict__ Q,
    const float* __restrict__ w)
{
    __shared__ uint16_t Ah[BM*PK], Al[BM*PK], Bh[BN*PK], Bl[BN*PK];
    int tid = threadIdx.x, lane = tid & 31, wid = tid >> 5;
    int wm = wid >> 1, wn = wid & 1;
    int b = blockIdx.z, n0 = blockIdx.y*BM, m0 = blockIdx.x*BN;
    const float* Cb = C + (size_t)b*Nn*Dd;
    const float* Qb = Q + (size_t)b*Mm*Dd;
    const float* w3 = w + 2*Dd;

    TileFrag<BM> fa; TileFrag<BN> fb;
    frag_load(fa, Cb, Dd, n0, 0, tid);
    frag_load(fb, Qb, Dd, m0, 0, tid);

    float acc[2][4][4] = {};
    for (int k0 = 0; k0 < Dd; k0 += BK){
        __syncthreads();
        frag_stage(fa, Ah, Al, w3, nullptr, k0, tid);
        frag_stage(fb, Bh, Bl, nullptr, nullptr, k0, tid);
        __syncthreads();
        if (k0 + BK < Dd){
            frag_load(fa, Cb, Dd, n0, k0 + BK, tid);
            frag_load(fb, Qb, Dd, m0, k0 + BK, tid);
        }
        warp_mma_tile(acc, Ah, Al, Bh, Bl, wm, wn, lane);
    }

    int rg = lane >> 2, cg = (lane & 3)*2;
#pragma unroll
    for (int mt = 0; mt < 2; mt++)
#pragma unroll
    for (int nt = 0; nt < 4; nt++)
#pragma unroll
    for (int h = 0; h < 2; h++){
        int n = n0 + wm*32 + mt*16 + rg + h*8;
        int m = m0 + wn*32 + nt*8 + cg;
        float rc = g_rowC[b*Nn + n];
        float2 o;
        o.x = __expf(acc[mt][nt][h*2+0] + rc + g_rowQ[b*Mm + m + 0]);
        o.y = __expf(acc[mt][nt][h*2+1] + rc + g_rowQ[b*Mm + m + 1]);
        *reinterpret_cast<float2*>(&g_E[(size_t)(b*Nn + n)*Mm + m]) = o;
    }
}

// ---------------------------------------------------------------------------
// gemmT: Tt[b,d,m] = rcpCol[m] * sum_n Ct[d,n] * (Cmask[n]? 0 : Et[m,n])
// ---------------------------------------------------------------------------
__global__ void __launch_bounds__(256) gemmT_mma(const int* __restrict__ Cmask)
{
    __shared__ uint16_t Ah[BM*PK], Al[BM*PK], Bh[BN*PK], Bl[BN*PK];
    int tid = threadIdx.x, lane = tid & 31, wid = tid >> 5;
    int wm = wid >> 1, wn = wid & 1;
    int b = blockIdx.z, d0 = blockIdx.y*BM, m0 = blockIdx.x*BN;
    const float* Ab = g_Ct + (size_t)b*Dd*Nn;   // [d][n]
    const float* Bp = g_Et + (size_t)b*Mm*Nn;   // [m][n]
    const int*   cm = Cmask + b*Nn;

    TileFrag<BM> fa; TileFrag<BN> fb;
    frag_load(fa, Ab, Nn, d0, 0, tid);
    frag_load(fb, Bp, Nn, m0, 0, tid);

    float acc[2][4][4] = {};
    for (int k0 = 0; k0 < Nn; k0 += BK){
        __syncthreads();
        frag_stage(fa, Ah, Al, nullptr, nullptr, k0, tid);
        frag_stage(fb, Bh, Bl, nullptr, cm, k0, tid);
        __syncthreads();
        if (k0 + BK < Nn){
            frag_load(fa, Ab, Nn, d0, k0 + BK, tid);
            frag_load(fb, Bp, Nn, m0, k0 + BK, tid);
        }
        warp_mma_tile(acc, Ah, Al, Bh, Bl, wm, wn, lane);
    }

    int rg = lane >> 2, cg = (lane & 3)*2;
#pragma unroll
    for (int mt = 0; mt < 2; mt++)
#pragma unroll
    for (int nt = 0; nt < 4; nt++)
#pragma unroll
    for (int h = 0; h < 2; h++){
        int d = d0 + wm*32 + mt*16 + rg + h*8;
        int m = m0 + wn*32 + nt*8 + cg;
        float2 o;
        o.x = acc[mt][nt][h*2+0] * g_rcpCol[b*Mm + m + 0];
        o.y = acc[mt][nt][h*2+1] * g_rcpCol[b*Mm + m + 1];
        *reinterpret_cast<float2*>(&g_Tt[((size_t)b*Dd + d)*Mm + m]) = o;
    }
}

// ---------------------------------------------------------------------------
// gemmAB: A   [b,n,d] = rcpRow[n] * sum_m E[n,m] * (Qmask[m]? 0 : Qt[d,m])
//         Bout[b,n,d] = rcpRow[n] * sum_m E[n,m] * (Qmask[m]? 0 : Tt[d,m])
// ---------------------------------------------------------------------------
__global__ void __launch_bounds__(256) gemmAB_mma(
    const int* __restrict__ Qmask, float* __restrict__ outA,
    float* __restrict__ outB)
{
    __shared__ uint16_t Ah[BM*PK], Al[BM*PK];
    __shared__ uint16_t B1h[BN*PK], B1l[BN*PK], B2h[BN*PK], B2l[BN*PK];
    int tid = threadIdx.x, lane = tid & 31, wid = tid >> 5;
    int wm = wid >> 1, wn = wid & 1;
    int b = blockIdx.z, n0 = blockIdx.y*BM, d0 = blockIdx.x*BN;
    const float* Eb  = g_E  + (size_t)b*Nn*Mm;   // [n][m]
    const float* Qtb = g_Qt + (size_t)b*Dd*Mm;   // [d][m]
    const float* Ttb = g_Tt + (size_t)b*Dd*Mm;   // [d][m]
    const int*   qm  = Qmask + b*Mm;

    TileFrag<BM> fa; TileFrag<BN> fb1, fb2;
    frag_load(fa,  Eb,  Mm, n0, 0, tid);
    frag_load(fb1, Qtb, Mm, d0, 0, tid);
    frag_load(fb2, Ttb, Mm, d0, 0, tid);

    float accA[2][4][4] = {};
    float accB[2][4][4] = {};
    for (int k0 = 0; k0 < Mm; k0 += BK){
        __syncthreads();
        frag_stage(fa,  Ah,  Al,  nullptr, nullptr, k0, tid);
        frag_stage(fb1, B1h, B1l, nullptr, qm, k0, tid);
        frag_stage(fb2, B2h, B2l, nullptr, qm, k0, tid);
        __syncthreads();
        if (k0 + BK < Mm){
            frag_load(fa,  Eb,  Mm, n0, k0 + BK, tid);
            frag_load(fb1, Qtb, Mm, d0, k0 + BK, tid);
            frag_load(fb2, Ttb, Mm, d0, k0 + BK, tid);
        }
        warp_mma_tile(accA, Ah, Al, B1h, B1l, wm, wn, lane);
        warp_mma_tile(accB, Ah, Al, B2h, B2l, wm, wn, lane);
    }

    int rg = lane >> 2, cg = (lane & 3)*2;
#pragma unroll
    for (int mt = 0; mt < 2; mt++)
#pragma unroll
    for (int nt = 0; nt < 4; nt++)
#pragma unroll
    for (int h = 0; h < 2; h++){
        int n = n0 + wm*32 + mt*16 + rg + h*8;
        int d = d0 + wn*32 + nt*8 + cg;
        float rr = g_rcpRow[b*Nn + n];
        size_t idx = (size_t)(b*Nn + n)*Dd + d;
        float2 oa = { accA[mt][nt][h*2+0]*rr, accA[mt][nt][h*2+1]*rr };
        float2 ob = { accB[mt][nt][h*2+0]*rr, accB[mt][nt][h*2+1]*rr };
        *reinterpret_cast<float2*>(&outA[idx]) = oa;
        *reinterpret_cast<float2*>(&outB[idx]) = ob;
    }
}

// ---------------------------------------------------------------------------
// Row-dot kernels
// ---------------------------------------------------------------------------
__global__ void rowdotC_kernel(const float* __restrict__ C, const float* __restrict__ w)
{
    int warp = (blockIdx.x * blockDim.x + threadIdx.x) >> 5;
    int lane = threadIdx.x & 31;
    if (warp >= Bb * Nn) return;
    const float4* x4 = reinterpret_cast<const float4*>(C + (size_t)warp * Dd);
    const float4* w4 = reinterpret_cast<const float4*>(w);
    float s = 0.f;
#pragma unroll
    for (int j = 0; j < 4; j++){
        float4 a = x4[lane + j*32]; float4 b = w4[lane + j*32];
        s += a.x*b.x + a.y*b.y + a.z*b.z + a.w*b.w;
    }
#pragma unroll
    for (int o = 16; o; o >>= 1) s += __shfl_xor_sync(~0u, s, o);
    if (lane == 0) g_rowC[warp] = s;
}

__global__ void rowdotQ_kernel(const float* __restrict__ Q, const float* __restrict__ w)
{
    int warp = (blockIdx.x * blockDim.x + threadIdx.x) >> 5;
    int lane = threadIdx.x & 31;
    if (warp >= Bb * Mm) return;
    const float4* x4 = reinterpret_cast<const float4*>(Q + (size_t)warp * Dd);
    const float4* w4 = reinterpret_cast<const float4*>(w + Dd);
    float s = 0.f;
#pragma unroll
    for (int j = 0; j < 4; j++){
        float4 a = x4[lane + j*32]; float4 b = w4[lane + j*32];
        s += a.x*b.x + a.y*b.y + a.z*b.z + a.w*b.w;
    }
#pragma unroll
    for (int o = 16; o; o >>= 1) s += __shfl_xor_sync(~0u, s, o);
    if (lane == 0) g_rowQ[warp] = s;
}

// ---------------------------------------------------------------------------
// Transpose kernels (32x32 tiles)
// ---------------------------------------------------------------------------
__device__ __forceinline__ void transpose_body(
    const float* __restrict__ src, float* __restrict__ dst, int rows, int cols)
{
    __shared__ float t[32][33];
    int b = blockIdx.z;
    const float* s = src + (size_t)b*rows*cols;
    float* d = dst + (size_t)b*rows*cols;
    int c0 = blockIdx.x*32, r0 = blockIdx.y*32;
    int tx = threadIdx.x & 31, ty = threadIdx.x >> 5;
#pragma unroll
    for (int j = 0; j < 4; j++)
        t[ty + 8*j][tx] = s[(size_t)(r0 + ty + 8*j)*cols + c0 + tx];
    __syncthreads();
#pragma unroll
    for (int j = 0; j < 4; j++)
        d[(size_t)(c0 + ty + 8*j)*rows + r0 + tx] = t[tx][ty + 8*j];
}
__global__ void __launch_bounds__(256) transposeC_kernel(const float* __restrict__ C)
{ transpose_body(C, g_Ct, Nn, Dd); }
__global__ void __launch_bounds__(256) transposeQ_kernel(const float* __restrict__ Q)
{ transpose_body(Q, g_Qt, Mm, Dd); }
__global__ void __launch_bounds__(256) transposeE_kernel()
{ transpose_body(g_E, g_Et, Nn, Mm); }

// ---------------------------------------------------------------------------
// Masked reductions -> reciprocals
// ---------------------------------------------------------------------------
__global__ void rowsum_kernel(const int* __restrict__ Qmask)
{
    int warp = (blockIdx.x * blockDim.x + threadIdx.x) >> 5;
    int lane = threadIdx.x & 31;
    if (warp >= Bb * Nn) return;
    int b = warp / Nn;
    const float4* e4 = reinterpret_cast<const float4*>(g_E + (size_t)warp * Mm);
    const int4*   q4 = reinterpret_cast<const int4*>(Qmask + b * Mm);
    float s = 0.f;
#pragma unroll
    for (int j = 0; j < 4; j++){
        float4 v = e4[lane + j*32];
        int4   q = q4[lane + j*32];
        s += (q.x ? 0.f : v.x) + (q.y ? 0.f : v.y) + (q.z ? 0.f : v.z) + (q.w ? 0.f : v.w);
    }
#pragma unroll
    for (int o = 16; o; o >>= 1) s += __shfl_xor_sync(~0u, s, o);
    if (lane == 0) g_rcpRow[warp] = 1.f / s;
}

__global__ void colsumT_kernel(const int* __restrict__ Cmask)
{
    int warp = (blockIdx.x * blockDim.x + threadIdx.x) >> 5;
    int lane = threadIdx.x & 31;
    if (warp >= Bb * Mm) return;
    int b = warp / Mm;
    const float4* e4 = reinterpret_cast<const float4*>(g_Et + (size_t)warp * Nn);
    const int4*   c4 = reinterpret_cast<const int4*>(Cmask + b * Nn);
    float s = 0.f;
#pragma unroll
    for (int j = 0; j < 16; j++){
        float4 v = e4[lane + j*32];
        int4   c = c4[lane + j*32];
        s += (c.x ? 0.f : v.x) + (c.y ? 0.f : v.y) + (c.z ? 0.f : v.z) + (c.w ? 0.f : v.w);
    }
#pragma unroll
    for (int o = 16; o; o >>= 1) s += __shfl_xor_sync(~0u, s, o);
    if (lane == 0) g_rcpCol[warp] = 1.f / s;
}

// ---------------------------------------------------------------------------
extern "C" void kernel_launch(void* const* d_in, const int* in_sizes, int n_in,
                              void* d_out, int out_size)
{
    const float* C     = (const float*)d_in[0];
    const float* Q     = (const float*)d_in[1];
    const int*   Cmask = (const int*)d_in[2];
    const int*   Qmask = (const int*)d_in[3];
    const float* w     = (const float*)d_in[4];

    float* outA = (float*)d_out;
    float* outB = outA + (size_t)Bb * Nn * Dd;

    // 1. row dots + input transposes
    rowdotC_kernel<<<(Bb*Nn)/8, 256>>>(C, w);
    rowdotQ_kernel<<<(Bb*Mm)/8, 256>>>(Q, w);
    transposeC_kernel<<<dim3(Dd/32, Nn/32, Bb), 256>>>(C);
    transposeQ_kernel<<<dim3(Dd/32, Mm/32, Bb), 256>>>(Q);

    // 2. E = exp(S)   (tensor core, bf16x3)
    gemmS_mma<<<dim3(Mm/BN, Nn/BM, Bb), 256>>>(C, Q, w);

    // 3. E^T + masked reductions
    transposeE_kernel<<<dim3(Mm/32, Nn/32, Bb), 256>>>();
    rowsum_kernel<<<(Bb*Nn)/8, 256>>>(Qmask);
    colsumT_kernel<<<(Bb*Mm)/8, 256>>>(Cmask);

    // 4. T^T (tensor core)
    gemmT_mma<<<dim3(Mm/BN, Dd/BM, Bb), 256>>>(Cmask);

    // 5. A and Bout (tensor core, fused)
    gemmAB_mma<<<dim3(Dd/BN, Nn/BM, Bb), 256>>>(Qmask, outA, outB);
}